// round 1
// baseline (speedup 1.0000x reference)
#include <cuda_runtime.h>

// Problem constants (fixed by the dataset)
#define IN      66
#define EN      50
#define AN      20
#define THREADS 128
#define ROWS    256          // batch rows per block (2 per thread)
#define XSTRIDE 67           // 67 is odd & coprime with 32 -> conflict-free row reads

// Dynamic shared memory layout (bytes). All offsets 16B-aligned.
#define OFF_EW2 0                               // u64[IN*EN]   packed {w,w} E weights : 26400
#define OFF_W2  (OFF_EW2 + IN*EN*8)             // u64[EN*AN]   packed {w,w} A_W[i]    : 8000
#define OFF_AB  (OFF_W2 + EN*AN*8)              // float[IN*AN] A_b                    : 5280
#define OFF_EB  (OFF_AB + IN*AN*4)              // float[64]    E_b (padded)           : 256
#define OFF_X   (OFF_EB + 64*4)                 // float[ROWS*XSTRIDE] x tile / out    : 68608
#define SMEM_BYTES (OFF_X + ROWS*XSTRIDE*4)     // = 108544 bytes -> 2 CTAs/SM

typedef unsigned long long u64;

__device__ __forceinline__ u64 pack2(float lo, float hi) {
    u64 r;
    asm("mov.b64 %0, {%1, %2};" : "=l"(r) : "f"(lo), "f"(hi));
    return r;
}
__device__ __forceinline__ float2 unpack2(u64 v) {
    float lo, hi;
    asm("mov.b64 {%0, %1}, %2;" : "=f"(lo), "=f"(hi) : "l"(v));
    return make_float2(lo, hi);
}
// Packed dual-lane fp32 FMA (Blackwell f32x2 pipe: 2x scalar FFMA throughput)
__device__ __forceinline__ u64 ffma2(u64 a, u64 b, u64 c) {
    u64 d;
    asm("fma.rn.f32x2 %0, %1, %2, %3;" : "=l"(d) : "l"(a), "l"(b), "l"(c));
    return d;
}

__device__ __forceinline__ float fast_tanh(float x) {
    // accurate to ~1e-7 rel; clamp avoids inf/inf for |x| large (tanh saturates by 15)
    x = fminf(fmaxf(x, -15.0f), 15.0f);
    float t = __expf(2.0f * x);
    return __fdividef(t - 1.0f, t + 1.0f);
}

__global__ void __launch_bounds__(THREADS, 2)
attn_fused_kernel(const float* __restrict__ x,
                  const float* __restrict__ E_W,
                  const float* __restrict__ E_b,
                  const float* __restrict__ A_W,
                  const float* __restrict__ A_b,
                  float* __restrict__ out,
                  int Btotal)
{
    extern __shared__ unsigned char smem[];
    u64*   s_EW2 = (u64*)(smem + OFF_EW2);
    u64*   s_w2  = (u64*)(smem + OFF_W2);
    float* s_Ab  = (float*)(smem + OFF_AB);
    float* s_Eb  = (float*)(smem + OFF_EB);
    float* s_x   = (float*)(smem + OFF_X);

    const int tid     = threadIdx.x;
    const int rowBase = blockIdx.x * ROWS;
    int nvalid = Btotal - rowBase;
    if (nvalid > ROWS) nvalid = ROWS;

    // ---- Stage weights (broadcast-replicated for f32x2) and the x tile ----
    for (int idx = tid; idx < IN * EN; idx += THREADS) {
        float w = E_W[idx];
        s_EW2[idx] = pack2(w, w);
    }
    for (int idx = tid; idx < IN * AN; idx += THREADS) s_Ab[idx] = A_b[idx];
    if (tid < EN) s_Eb[tid] = E_b[tid];

    const float* xg = x + (size_t)rowBase * IN;
    for (int idx = tid; idx < nvalid * IN; idx += THREADS) {
        int r = idx / IN;
        int k = idx - r * IN;
        s_x[r * XSTRIDE + k] = xg[idx];   // coalesced global read
    }
    __syncthreads();

    // Thread t owns rows (rowBase + t) and (rowBase + t + 128): both stride-67
    // shared reads are conflict-free across the warp.
    float* xr0 = s_x + tid * XSTRIDE;
    float* xr1 = s_x + (tid + THREADS) * XSTRIDE;

    // ---- E = tanh(x @ E_W + E_b), packed over the two rows ----
    u64 E2[EN];
    #pragma unroll
    for (int e = 0; e < EN; e++) { float b = s_Eb[e]; E2[e] = pack2(b, b); }

    for (int k = 0; k < IN; k++) {
        u64 xk = pack2(xr0[k], xr1[k]);
        const ulonglong2* wr = (const ulonglong2*)(s_EW2 + k * EN);  // 25 x LDS.128 (broadcast)
        #pragma unroll
        for (int e2 = 0; e2 < EN / 2; e2++) {
            ulonglong2 w = wr[e2];
            E2[2 * e2]     = ffma2(xk, w.x, E2[2 * e2]);
            E2[2 * e2 + 1] = ffma2(xk, w.y, E2[2 * e2 + 1]);
        }
    }
    #pragma unroll
    for (int e = 0; e < EN; e++) {
        float2 v = unpack2(E2[e]);
        E2[e] = pack2(fast_tanh(v.x), fast_tanh(v.y));
    }

    // ---- Per-feature attention: for each i, scores = E @ A_W[i] + A_b[i] ----
    const float4* Aw4 = (const float4*)A_W;   // A_W[i] = 1000 floats = 250 float4
    for (int i = 0; i < IN; i++) {
        __syncthreads();   // previous iteration done reading s_w2
        const float4* gw = Aw4 + i * (EN * AN / 4);
        for (int idx = tid; idx < EN * AN / 4; idx += THREADS) {
            float4 w = gw[idx];
            u64* d = s_w2 + idx * 4;
            d[0] = pack2(w.x, w.x);
            d[1] = pack2(w.y, w.y);
            d[2] = pack2(w.z, w.z);
            d[3] = pack2(w.w, w.w);
        }
        __syncthreads();

        u64 sc[AN];
        const float* ab = s_Ab + i * AN;
        #pragma unroll
        for (int a = 0; a < AN; a++) { float b = ab[a]; sc[a] = pack2(b, b); }

        const ulonglong2* w2 = (const ulonglong2*)s_w2;
        #pragma unroll 5
        for (int e = 0; e < EN; e++) {
            u64 Ee = E2[e];
            const ulonglong2* wr = w2 + e * (AN / 2);   // broadcast LDS.128
            #pragma unroll
            for (int a2 = 0; a2 < AN / 2; a2++) {
                ulonglong2 w = wr[a2];
                sc[2 * a2]     = ffma2(Ee, w.x, sc[2 * a2]);
                sc[2 * a2 + 1] = ffma2(Ee, w.y, sc[2 * a2 + 1]);
            }
        }

        // softmax over the 20 logits (both rows), keep class-1 prob
        float m0 = -1e30f, m1 = -1e30f;
        #pragma unroll
        for (int a = 0; a < AN; a++) {
            float2 v = unpack2(sc[a]);
            m0 = fmaxf(m0, v.x);
            m1 = fmaxf(m1, v.y);
        }
        float sum0 = 0.0f, sum1 = 0.0f, p0 = 0.0f, p1 = 0.0f;
        #pragma unroll
        for (int a = 0; a < AN; a++) {
            float2 v  = unpack2(sc[a]);
            float e0 = __expf(v.x - m0);
            float e1 = __expf(v.y - m1);
            sum0 += e0; sum1 += e1;
            if (a == 1) { p0 = e0; p1 = e1; }
        }
        // out[b,i] = x[b,i] * p1/sum ; overwrite x tile in place (x[.,i] dead after this)
        xr0[i] = xr0[i] * __fdividef(p0, sum0);
        xr1[i] = xr1[i] * __fdividef(p1, sum1);
    }

    __syncthreads();
    float* og = out + (size_t)rowBase * IN;
    for (int idx = tid; idx < nvalid * IN; idx += THREADS) {
        int r = idx / IN;
        int k = idx - r * IN;
        og[idx] = s_x[r * XSTRIDE + k];   // coalesced global write
    }
}

extern "C" void kernel_launch(void* const* d_in, const int* in_sizes, int n_in,
                              void* d_out, int out_size)
{
    const float* x   = (const float*)d_in[0];
    const float* E_W = (const float*)d_in[1];
    const float* E_b = (const float*)d_in[2];
    const float* A_W = (const float*)d_in[3];
    const float* A_b = (const float*)d_in[4];
    float* out = (float*)d_out;

    const int Btotal = in_sizes[0] / IN;
    const int grid   = (Btotal + ROWS - 1) / ROWS;

    cudaFuncSetAttribute(attn_fused_kernel,
                         cudaFuncAttributeMaxDynamicSharedMemorySize, SMEM_BYTES);
    attn_fused_kernel<<<grid, THREADS, SMEM_BYTES>>>(x, E_W, E_b, A_W, A_b, out, Btotal);
}